// round 8
// baseline (speedup 1.0000x reference)
#include <cuda_runtime.h>

// ---------------------------------------------------------------------------
// SimpleRNN: 2-layer bidirectional tanh RNN + FC head.  B=32,T=2048,H=512.
//  - recurrence: Whh register-resident, fma.f32x2; h broadcast across 8-CTA
//    cluster via plain remote st.shared::cluster + fence + remote mbarrier
//    arrives (count=8); 2 batch-pair pipelines hide DSMEM latency.
//  - GEMMs: 128x128x16 tiles, f32x2 packed FMA along M, B duplicated in SMEM.
// ---------------------------------------------------------------------------

#define B_   32
#define T_   2048
#define H_   512
#define V_   8192
#define BT_  (B_ * T_)     // 65536
#define NW_  1024          // 2*H

__device__ float g_WihT[2 * V_ * H_];     //  33.5 MB
__device__ float g_pre [67108864];        // 268 MB  [BT][1024]
__device__ float g_hcat[67108864];        // 268 MB  [BT][1024]

// ---------------------------------------------------------------------------
// 1) Transpose Wih0 [2][H][V] -> g_WihT [2][V][H]
// ---------------------------------------------------------------------------
__global__ void transpose_k(const float* __restrict__ Wih0)
{
    __shared__ float tile[32][33];
    int d  = blockIdx.z;
    const float* S = Wih0   + (size_t)d * H_ * V_;
    float*       D = g_WihT + (size_t)d * V_ * H_;
    int v0 = blockIdx.x * 32;
    int h0 = blockIdx.y * 32;
    int tx = threadIdx.x, ty = threadIdx.y;
#pragma unroll
    for (int i = 0; i < 4; i++)
        tile[ty + 8 * i][tx] = S[(size_t)(h0 + ty + 8 * i) * V_ + v0 + tx];
    __syncthreads();
#pragma unroll
    for (int i = 0; i < 4; i++)
        D[(size_t)(v0 + ty + 8 * i) * H_ + h0 + tx] = tile[tx][ty + 8 * i];
}

// ---------------------------------------------------------------------------
// 2) Gather + biases -> g_pre
// ---------------------------------------------------------------------------
__global__ void gather_k(const int* __restrict__ x,
                         const float* __restrict__ bih0,
                         const float* __restrict__ bhh0)
{
    int bt  = blockIdx.x;
    int idx = __ldg(&x[bt]);
    int o   = threadIdx.x * 4;
    int dir = o >> 9;
    int h   = o & 511;
    float4 w  = *(const float4*)&g_WihT[((size_t)dir * V_ + idx) * H_ + h];
    float4 b1 = *(const float4*)&bih0[o];
    float4 b2 = *(const float4*)&bhh0[o];
    float4 r;
    r.x = w.x + b1.x + b2.x;
    r.y = w.y + b1.y + b2.y;
    r.z = w.z + b1.z + b2.z;
    r.w = w.w + b1.w + b2.w;
    *(float4*)&g_pre[(size_t)bt * NW_ + o] = r;
}

// ---------------------------------------------------------------------------
// dummy: positions rnn_layer_k as the 6th launch so ncu (-s 5 -c 1) captures it
// ---------------------------------------------------------------------------
__global__ void dummy_k() {}

// ---------------------------------------------------------------------------
// 3/5) Recurrence. 16 clusters x 8 CTAs. CTA rank owns 64 Whh rows in REGS.
// Two batch-pair groups g={0,1}, double-buffered h, count-8 mbarriers.
// h-buffer per (g,buf): [owner 0..7][132 floats] = [2 batches][64 rows]+pad.
// Broadcast: remote scalar STS (quad lanes 0,1 -> peers 0..3; lanes 2,3 ->
// peers 4..7), then tid0: fence.acq_rel.cluster + 8 remote mbarrier arrives.
// ---------------------------------------------------------------------------
#define FMA2(d, a, b) \
    asm("fma.rn.f32x2 %0, %1, %2, %0;" : "+l"(d) : "l"(a), "l"(b))

__global__ void __cluster_dims__(8, 1, 1) __launch_bounds__(256, 1)
rnn_layer_k(const float* __restrict__ Whh)
{
    __shared__ __align__(16) float s_h[2][2][1056];         // [g][buf][8*132]
    __shared__ __align__(8)  unsigned long long s_mbar[4];  // [g*2+buf]

    int tid  = threadIdx.x;
    int rank = blockIdx.x & 7;
    int cid  = blockIdx.x >> 3;
    int dir  = cid >> 3;
    int b0   = (cid & 7) * 4;

    int kq   = tid & 3;                  // quad lane
    int r    = tid >> 2;                 // 0..63
    int grow = rank * 64 + r;
    int colbase = dir * H_ + grow;
    int bsel  = kq & 1;                  // batch within group
    int phalf = (kq >> 1) * 4;           // which 4 peers this lane serves

    // --- my 128-float Whh chunk in registers (64 packed u64) ---
    unsigned long long wp[64];
    const unsigned long long* Wrow = (const unsigned long long*)
        (Whh + ((size_t)dir * H_ + grow) * H_ + kq * 128);
#pragma unroll
    for (int i = 0; i < 64; i++) wp[i] = Wrow[i];

    // --- zero h buffers, init count-8 mbarriers ---
    for (int i = tid; i < 2 * 2 * 1056; i += 256) ((float*)s_h)[i] = 0.0f;
    unsigned int hbase = (unsigned int)__cvta_generic_to_shared(&s_h[0][0][0]);
    unsigned int mbase = (unsigned int)__cvta_generic_to_shared(&s_mbar[0]);
    if (tid == 0) {
#pragma unroll
        for (int i = 0; i < 4; i++)
            asm volatile("mbarrier.init.shared.b64 [%0], %1;"
                         :: "r"(mbase + i * 8), "r"(8) : "memory");
    }
    __syncthreads();
    asm volatile("barrier.cluster.arrive.aligned;" ::: "memory");
    asm volatile("barrier.cluster.wait.aligned;" ::: "memory");

    unsigned int peer[8];
    unsigned int mdelta = mbase - hbase;
#pragma unroll
    for (int p = 0; p < 8; p++)
        asm volatile("mapa.shared::cluster.u32 %0, %1, %2;"
                     : "=r"(peer[p]) : "r"(hbase), "r"(p));

    // pv prefetch (all 4 lanes: batch = b0 + 2g + bsel)
    float pv[2];
#pragma unroll
    for (int g = 0; g < 2; g++)
        pv[g] = __ldg(&g_pre[(((size_t)(b0 + 2 * g + bsel) * T_ +
                               (dir ? (T_ - 1) : 0)) << 10) + colbase]);

    for (int t = 0; t < T_; t++) {
        int b   = t & 1;
        unsigned int par = (unsigned)((((t + 1) >> 1) - 1) & 1);
#pragma unroll
        for (int g = 0; g < 2; g++) {
            unsigned int mb = mbase + (unsigned)((g * 2 + b) * 8);

            // 1) wait for this buffer's 8 arrivals (t=0 reads zero-init)
            if (t > 0) {
                unsigned int done;
                asm volatile(
                    "{\n\t.reg .pred p;\n\t"
                    "mbarrier.try_wait.parity.acquire.cluster.shared::cta.b64 p, [%1], %2;\n\t"
                    "selp.b32 %0, 1, 0, p;\n\t}"
                    : "=r"(done) : "r"(mb), "r"(par) : "memory");
                if (!done) {
                    asm volatile(
                        "{\n\t.reg .pred P1;\n\t"
                        "WL_%=:\n\t"
                        "mbarrier.try_wait.parity.acquire.cluster.shared::cta.b64 P1, [%0], %1, 0x989680;\n\t"
                        "@P1 bra.uni WD_%=;\n\t"
                        "bra.uni WL_%=;\n\t"
                        "WD_%=:\n\t}"
                        :: "r"(mb), "r"(par) : "memory");
                }
            }

            // 2) partial dots: owners 2kq, 2kq+1; both batches of this group
            const ulonglong2* hp = (const ulonglong2*)&s_h[g][b][0];
            unsigned long long a0 = 0ULL, a1 = 0ULL;
#pragma unroll
            for (int o = 0; o < 2; o++) {
                int ob = (2 * kq + o) * 33;      // owner block, 16B units
#pragma unroll
                for (int j = 0; j < 16; j++) {
                    ulonglong2 h0 = hp[ob + j];       // batch-local 0
                    ulonglong2 h1 = hp[ob + 16 + j];  // batch-local 1
                    int wi = o * 32 + 2 * j;
                    FMA2(a0, wp[wi], h0.x); FMA2(a0, wp[wi + 1], h0.y);
                    FMA2(a1, wp[wi], h1.x); FMA2(a1, wp[wi + 1], h1.y);
                }
            }
            float s0, s1;
            {
                float lo, hi;
                asm("mov.b64 {%0, %1}, %2;" : "=f"(lo), "=f"(hi) : "l"(a0)); s0 = lo + hi;
                asm("mov.b64 {%0, %1}, %2;" : "=f"(lo), "=f"(hi) : "l"(a1)); s1 = lo + hi;
            }
            s0 += __shfl_xor_sync(0xffffffffu, s0, 1);
            s1 += __shfl_xor_sync(0xffffffffu, s1, 1);
            s0 += __shfl_xor_sync(0xffffffffu, s0, 2);
            s1 += __shfl_xor_sync(0xffffffffu, s1, 2);
            float sel = bsel ? s1 : s0;
            float hn  = tanhf(pv[g] + sel);

            // 3) global store (one lane per value) + pv prefetch (all lanes)
            size_t batch = (size_t)(b0 + 2 * g + bsel);
            int tt = dir ? (T_ - 1 - t) : t;
            if (kq < 2)
                g_hcat[((batch * T_ + tt) << 10) + colbase] = hn;
            if (t < T_ - 1) {
                int tn = dir ? (T_ - 2 - t) : (t + 1);
                pv[g] = __ldg(&g_pre[((batch * T_ + tn) << 10) + colbase]);

                // 4) remote stores into my 4 peers' buf b^1
                unsigned int off = (unsigned)(((g * 2 + (b ^ 1)) * 1056 +
                                               rank * 132 + bsel * 64 + r) * 4);
#pragma unroll
                for (int c = 0; c < 4; c++)
                    asm volatile("st.shared::cluster.f32 [%0], %1;"
                                 :: "r"(peer[phalf + c] + off), "f"(hn) : "memory");
            }

            // 5) all stores issued + all reads of buf b complete
            __syncthreads();

            // 6) publish: fence + one arrive per peer barrier
            if (tid == 0 && t < T_ - 1) {
                asm volatile("fence.acq_rel.cluster;" ::: "memory");
                unsigned int moff = mdelta + (unsigned)((g * 2 + (b ^ 1)) * 8);
#pragma unroll
                for (int p = 0; p < 8; p++)
                    asm volatile("mbarrier.arrive.shared::cluster.b64 _, [%0];"
                                 :: "r"(peer[p] + moff) : "memory");
            }
        }
    }
    asm volatile("barrier.cluster.arrive.aligned;" ::: "memory");
    asm volatile("barrier.cluster.wait.aligned;" ::: "memory");
}

// ---------------------------------------------------------------------------
// 4/6) C[m][n] = sum_k g_hcat[m][k] * Bw[n][k] + bias1[n] (+ bias2[n])
// M=65536, N=1024, K=1024. BM=128, BN=128, BK=16, 256 thr, 8x8 microtile,
// f32x2 packed along M. B stored DUPLICATED in SMEM as (v,v) u64 pairs:
//   Bd[k][c][tx][2]  with k-stride 276, c-stride 68 (both ≡4 mod 8 floats ->
//   warp's kk quarter spreads banks; 16B-aligned for LDS.128 reads).
// As stride 132 (same reasoning).
// ---------------------------------------------------------------------------
__global__ __launch_bounds__(256, 2)
void gemm_k(const float* __restrict__ Bw,
            const float* __restrict__ bias1,
            const float* __restrict__ bias2,
            float* __restrict__ Cext,
            int use_pre)
{
    __shared__ __align__(16) float As[16 * 132];   // [k][m]
    __shared__ __align__(16) float Bd[16 * 276];   // [k][c:68][tx:4]

    float* C = use_pre ? g_pre : Cext;
    int m0 = blockIdx.y * 128;
    int n0 = blockIdx.x * 128;
    int tid = threadIdx.x;
    int tx = tid & 15;               // n-group: cols n0 + tx*8 .. +8
    int ty = tid >> 4;               // m-group: rows m0 + ty*8 .. +8

    unsigned long long acc[4][8];
#pragma unroll
    for (int i = 0; i < 4; i++)
#pragma unroll
        for (int j = 0; j < 8; j++) acc[i][j] = 0ULL;

    for (int kt = 0; kt < 1024; kt += 16) {
#pragma unroll
        for (int i = 0; i < 2; i++) {
            int j  = tid + 256 * i;
            int m  = j >> 2, kk = j & 3;
            float4 va = *(const float4*)&g_hcat[(size_t)(m0 + m) * 1024 + kt + kk * 4];
            As[(kk * 4 + 0) * 132 + m] = va.x;
            As[(kk * 4 + 1) * 132 + m] = va.y;
            As[(kk * 4 + 2) * 132 + m] = va.z;
            As[(kk * 4 + 3) * 132 + m] = va.w;
            // B row n = m: dup-store (v,v) at Bd[k*276 + c*68 + w*4 + (n&1)*2]
            float4 vb = *(const float4*)&Bw[(size_t)(n0 + m) * 1024 + kt + kk * 4];
            int bcol = ((m & 7) >> 1) * 68 + (m >> 3) * 4 + (m & 1) * 2;
            float2 d0 = make_float2(vb.x, vb.x);
            float2 d1 = make_float2(vb.y, vb.y);
            float2 d2 = make_float2(vb.z, vb.z);
            float2 d3 = make_float2(vb.w, vb.w);
            *(float2*)&Bd[(kk * 4 + 0) * 276 + bcol] = d0;
            *(float2*)&Bd[(kk * 4 + 1) * 276 + bcol] = d1;
            *(float2*)&Bd[(kk * 4 + 2) * 276 + bcol] = d2;
            *(float2*)&Bd[(kk * 4 + 3) * 276 + bcol] = d3;
        }
        __syncthreads();

#pragma unroll
        for (int k = 0; k < 16; k++) {
            const ulonglong2* ap = (const ulonglong2*)(As + k * 132 + ty * 8);
            ulonglong2 av0 = ap[0], av1 = ap[1];
            unsigned long long a[4] = {av0.x, av0.y, av1.x, av1.y};
            unsigned long long b[8];
#pragma unroll
            for (int c = 0; c < 4; c++) {
                ulonglong2 bp = *(const ulonglong2*)&Bd[k * 276 + c * 68 + tx * 4];
                b[2 * c]     = bp.x;
                b[2 * c + 1] = bp.y;
            }
#pragma unroll
            for (int i = 0; i < 4; i++)
#pragma unroll
                for (int j = 0; j < 8; j++)
                    FMA2(acc[i][j], a[i], b[j]);
        }
        __syncthreads();
    }

    float bs[8];
#pragma unroll
    for (int j = 0; j < 8; j++) {
        int n = n0 + tx * 8 + j;
        bs[j] = bias1[n] + (bias2 ? bias2[n] : 0.0f);
    }
#pragma unroll
    for (int i = 0; i < 4; i++) {
        float lo[8], hi[8];
#pragma unroll
        for (int j = 0; j < 8; j++) {
            float l, h;
            asm("mov.b64 {%0, %1}, %2;" : "=f"(l), "=f"(h) : "l"(acc[i][j]));
            lo[j] = l; hi[j] = h;
        }
        size_t row0 = (size_t)(m0 + ty * 8 + 2 * i) * 1024 + n0 + tx * 8;
        float4 r0, r1, r2, r3;
        r0.x = lo[0] + bs[0]; r0.y = lo[1] + bs[1]; r0.z = lo[2] + bs[2]; r0.w = lo[3] + bs[3];
        r1.x = lo[4] + bs[4]; r1.y = lo[5] + bs[5]; r1.z = lo[6] + bs[6]; r1.w = lo[7] + bs[7];
        r2.x = hi[0] + bs[0]; r2.y = hi[1] + bs[1]; r2.z = hi[2] + bs[2]; r2.w = hi[3] + bs[3];
        r3.x = hi[4] + bs[4]; r3.y = hi[5] + bs[5]; r3.z = hi[6] + bs[6]; r3.w = hi[7] + bs[7];
        *(float4*)&C[row0]            = r0;
        *(float4*)&C[row0 + 4]        = r1;
        *(float4*)&C[row0 + 1024]     = r2;
        *(float4*)&C[row0 + 1024 + 4] = r3;
    }
}

// ---------------------------------------------------------------------------
extern "C" void kernel_launch(void* const* d_in, const int* in_sizes, int n_in,
                              void* d_out, int out_size)
{
    const int*   x    = (const int*)  d_in[0];
    const float* Wih0 = (const float*)d_in[1];
    const float* Whh0 = (const float*)d_in[2];
    const float* bih0 = (const float*)d_in[3];
    const float* bhh0 = (const float*)d_in[4];
    const float* Wih1 = (const float*)d_in[5];
    const float* Whh1 = (const float*)d_in[6];
    const float* bih1 = (const float*)d_in[7];
    const float* bhh1 = (const float*)d_in[8];
    const float* fcW  = (const float*)d_in[9];
    const float* fcb  = (const float*)d_in[10];
    float* out = (float*)d_out;

    transpose_k<<<dim3(V_ / 32, H_ / 32, 2), dim3(32, 8)>>>(Wih0);     // 1
    gather_k<<<BT_, 256>>>(x, bih0, bhh0);                             // 2
    rnn_layer_k<<<128, 256>>>(Whh0);                                   // 3
    gemm_k<<<dim3(8, BT_ / 128), 256>>>(Wih1, bih1, bhh1, nullptr, 1); // 4
    dummy_k<<<1, 32>>>();                                              // 5
    rnn_layer_k<<<128, 256>>>(Whh1);                                   // 6  <- ncu
    gemm_k<<<dim3(8, BT_ / 128), 256>>>(fcW, fcb, nullptr, out, 0);    // 7
}